// round 1
// baseline (speedup 1.0000x reference)
#include <cuda_runtime.h>
#include <cuda_bf16.h>
#include <math.h>

// Problem constants (fixed by setup_inputs)
#define NN      262144      // total points
#define HH      192         // hidden dim
#define SS      16384       // total supernodes
#define EE      524288      // edges
#define IND     16          // input feat dim
#define MAXDEG  32

// Scratch (device globals — no allocation allowed)
__device__ float g_x[(size_t)NN * HH];     // node features after input proj + pos embed
__device__ float g_y[(size_t)NN * HH];     // x @ W1_top
__device__ float g_xs[(size_t)SS * HH];    // gathered supernode features
__device__ float g_z[(size_t)SS * HH];     // x_sup @ W1_bot + b1
__device__ float g_pool[(size_t)SS * HH];  // pooled GELU activations

// ---------------------------------------------------------------------------
// K1: x[n,c] = (feat[n] @ W_in)[c] + b_in[c] + sincos_embed(pos[n])[c]
// one block per node, 192 threads (one per channel)
// ---------------------------------------------------------------------------
__global__ void node_embed_kernel(const float* __restrict__ feat,
                                  const float* __restrict__ pos,
                                  const float* __restrict__ W_in,
                                  const float* __restrict__ b_in) {
    int n = blockIdx.x;
    int c = threadIdx.x;
    __shared__ float f[IND];
    __shared__ float p[3];
    if (c < IND) f[c] = feat[n * IND + c];
    else if (c < IND + 3) p[c - IND] = pos[n * 3 + (c - IND)];
    __syncthreads();

    // sincos embed: channel c -> dim d = c/64, t = c%64; sin for t<32, cos else
    int d = c >> 6;
    int t = c & 63;
    int j = t & 31;
    // omega_j = 10000^(-j/32) = exp2(-j * log2(10000)/32)
    float omega = exp2f(-(float)j * (13.2877123795494f / 32.0f));
    float arg = p[d] * omega;
    float emb = (t < 32) ? sinf(arg) : cosf(arg);

    float acc = b_in[c] + emb;
#pragma unroll
    for (int i = 0; i < IND; i++)
        acc = fmaf(f[i], W_in[i * HH + c], acc);
    g_x[(size_t)n * HH + c] = acc;
}

// ---------------------------------------------------------------------------
// Gather supernode rows of g_x into g_xs
// ---------------------------------------------------------------------------
__global__ void gather_rows_kernel(const int* __restrict__ sup_idx) {
    int s = blockIdx.x;
    int c = threadIdx.x;
    int node = sup_idx[s];
    g_xs[(size_t)s * HH + c] = g_x[(size_t)node * HH + c];
}

// ---------------------------------------------------------------------------
// GEMM: C[M,192] = A[M,192] @ B[192,192] (+ bias)
// BM=64, BN=192 (full), BK=16, 256 threads, 8x6 micro-tile per thread
// ---------------------------------------------------------------------------
__global__ void gemm192_kernel(const float* __restrict__ A,
                               const float* __restrict__ B,
                               const float* __restrict__ bias,
                               float* __restrict__ C) {
    __shared__ float As[16][65];    // [k][m], padded to kill STS conflicts
    __shared__ float Bs[16][192];   // [k][n]

    int tid = threadIdx.x;
    int m0 = blockIdx.x * 64;
    int tr = tid >> 5;   // 0..7  (warp id) -> 8 rows each
    int tc = tid & 31;   // 0..31 -> 6 cols each

    float acc[8][6];
#pragma unroll
    for (int i = 0; i < 8; i++)
#pragma unroll
        for (int j = 0; j < 6; j++) acc[i][j] = 0.0f;

    for (int k0 = 0; k0 < 192; k0 += 16) {
        // load A tile: 64x16 = 1024 elems, 4 per thread (coalesced along k)
#pragma unroll
        for (int i = 0; i < 4; i++) {
            int idx = tid + 256 * i;
            int m = idx >> 4, k = idx & 15;
            As[k][m] = A[(size_t)(m0 + m) * HH + k0 + k];
        }
        // load B tile: 16x192 = 3072 elems, 12 per thread (coalesced along n)
#pragma unroll
        for (int i = 0; i < 12; i++) {
            int idx = tid + 256 * i;
            int k = idx / 192, n = idx - k * 192;
            Bs[k][n] = B[(size_t)(k0 + k) * HH + n];
        }
        __syncthreads();

#pragma unroll
        for (int kk = 0; kk < 16; kk++) {
            float a[8], b[6];
#pragma unroll
            for (int i = 0; i < 8; i++) a[i] = As[kk][tr * 8 + i];   // warp-broadcast
#pragma unroll
            for (int j = 0; j < 6; j++) b[j] = Bs[kk][tc * 6 + j];
#pragma unroll
            for (int i = 0; i < 8; i++)
#pragma unroll
                for (int j = 0; j < 6; j++)
                    acc[i][j] = fmaf(a[i], b[j], acc[i][j]);
        }
        __syncthreads();
    }

#pragma unroll
    for (int i = 0; i < 8; i++) {
        size_t row = (size_t)(m0 + tr * 8 + i) * HH;
#pragma unroll
        for (int j = 0; j < 6; j++) {
            int col = tc * 6 + j;
            float v = acc[i][j];
            if (bias) v += bias[col];
            C[row + col] = v;
        }
    }
}

// ---------------------------------------------------------------------------
// K3: pooled GELU. One block per supernode, 192 threads.
// Edges for supernode s are [32s, 32s+32); fan-in is exactly 32.
// pool[s,c] = (1/32) * sum_e GELU(y[src_e, c] + z[s, c])
// ---------------------------------------------------------------------------
__device__ __forceinline__ float gelu_exact(float v) {
    return 0.5f * v * (1.0f + erff(v * 0.70710678118654752f));
}

__global__ void pool_kernel(const int* __restrict__ src_idx) {
    int s = blockIdx.x;
    int c = threadIdx.x;
    __shared__ int srcs[MAXDEG];
    if (c < MAXDEG) srcs[c] = src_idx[s * MAXDEG + c];
    __syncthreads();

    float zc = g_z[(size_t)s * HH + c];
    float acc = 0.0f;
#pragma unroll 4
    for (int e = 0; e < MAXDEG; e++) {
        float v = g_y[(size_t)srcs[e] * HH + c] + zc;
        acc += gelu_exact(v);
    }
    g_pool[(size_t)s * HH + c] = acc * (1.0f / 32.0f);
}

// ---------------------------------------------------------------------------
// launch
// ---------------------------------------------------------------------------
extern "C" void kernel_launch(void* const* d_in, const int* in_sizes, int n_in,
                              void* d_out, int out_size) {
    const float* feat  = (const float*)d_in[0];   // [N,16]
    const float* pos   = (const float*)d_in[1];   // [N,3]
    const int*   sup   = (const int*)  d_in[2];   // [S]
    // d_in[3] = batch_idx (unused)
    const int*   src   = (const int*)  d_in[4];   // [E]
    // d_in[5] = dst_idx (structure implied: dst of edge e is supernode e/32)
    const float* W_in  = (const float*)d_in[6];   // [16,192]
    const float* b_in  = (const float*)d_in[7];   // [192]
    const float* W1    = (const float*)d_in[8];   // [384,192]
    const float* b1    = (const float*)d_in[9];   // [192]
    const float* W2    = (const float*)d_in[10];  // [192,192]
    const float* b2    = (const float*)d_in[11];  // [192]
    float* out = (float*)d_out;                   // [B,Q,192] == [S,192]

    float *px, *py, *pxs, *pz, *ppool;
    cudaGetSymbolAddress((void**)&px,    g_x);
    cudaGetSymbolAddress((void**)&py,    g_y);
    cudaGetSymbolAddress((void**)&pxs,   g_xs);
    cudaGetSymbolAddress((void**)&pz,    g_z);
    cudaGetSymbolAddress((void**)&ppool, g_pool);

    // 1) node features: x = feat @ W_in + b_in + sincos(pos)
    node_embed_kernel<<<NN, HH>>>(feat, pos, W_in, b_in);

    // 2) gather supernode rows
    gather_rows_kernel<<<SS, HH>>>(sup);

    // 3) y = x @ W1_top  (the big GEMM: 262144 x 192 x 192)
    gemm192_kernel<<<NN / 64, 256>>>(px, W1, nullptr, py);

    // 4) z = x_sup @ W1_bot + b1
    gemm192_kernel<<<SS / 64, 256>>>(pxs, W1 + (size_t)HH * HH, b1, pz);

    // 5) pooled GELU activations (fan-in 32 per supernode)
    pool_kernel<<<SS, HH>>>(src);

    // 6) out = pool @ W2 + b2
    gemm192_kernel<<<SS / 64, 256>>>(ppool, W2, b2, out);
}

// round 3
// speedup vs baseline: 1.2911x; 1.2911x over previous
#include <cuda_runtime.h>
#include <math.h>
#include <stdint.h>

// Problem constants (fixed by setup_inputs)
#define NN      262144
#define HH      192
#define SS      16384
#define IND     16
#define MAXDEG  32

// ---------------- device scratch (no allocation allowed) -------------------
__device__ float g_x[(size_t)NN * HH];     // node features after proj+embed
__device__ float g_y[(size_t)NN * HH];     // x @ W1_top
__device__ float g_xs[(size_t)SS * HH];    // gathered supernode features
__device__ float g_z[(size_t)SS * HH];     // x_sup @ W1_bot + b1
__device__ float g_pool[(size_t)SS * HH];  // pooled GELU activations
// transposed tf32-split weights, layout [n][k]
__device__ uint32_t g_w1a_hi[HH * HH], g_w1a_lo[HH * HH];
__device__ uint32_t g_w1b_hi[HH * HH], g_w1b_lo[HH * HH];
__device__ uint32_t g_w2_hi[HH * HH],  g_w2_lo[HH * HH];

// ---------------- helpers ---------------------------------------------------
__device__ __forceinline__ uint32_t f2tf32(float x) {
    uint32_t r;
    asm("cvt.rna.tf32.f32 %0, %1;" : "=r"(r) : "f"(x));
    return r;
}

__device__ __forceinline__ void mma_tf32(float c[4],
                                         uint32_t a0, uint32_t a1,
                                         uint32_t a2, uint32_t a3,
                                         uint32_t b0, uint32_t b1) {
    asm volatile(
        "mma.sync.aligned.m16n8k8.row.col.f32.tf32.tf32.f32 "
        "{%0,%1,%2,%3}, {%4,%5,%6,%7}, {%8,%9}, {%0,%1,%2,%3};"
        : "+f"(c[0]), "+f"(c[1]), "+f"(c[2]), "+f"(c[3])
        : "r"(a0), "r"(a1), "r"(a2), "r"(a3), "r"(b0), "r"(b1));
}

// ---------------------------------------------------------------------------
// K1: x[n,c] = (feat[n] @ W_in)[c] + b_in[c] + sincos_embed(pos[n])[c]
// ---------------------------------------------------------------------------
__global__ void node_embed_kernel(const float* __restrict__ feat,
                                  const float* __restrict__ pos,
                                  const float* __restrict__ W_in,
                                  const float* __restrict__ b_in) {
    int n = blockIdx.x;
    int c = threadIdx.x;
    __shared__ float f[IND];
    __shared__ float p[3];
    if (c < IND) f[c] = feat[n * IND + c];
    else if (c < IND + 3) p[c - IND] = pos[n * 3 + (c - IND)];
    __syncthreads();

    int d = c >> 6;
    int t = c & 63;
    int j = t & 31;
    float omega = exp2f(-(float)j * (13.2877123795494f / 32.0f));
    float arg = p[d] * omega;
    float emb = (t < 32) ? sinf(arg) : cosf(arg);

    float acc = b_in[c] + emb;
#pragma unroll
    for (int i = 0; i < IND; i++)
        acc = fmaf(f[i], W_in[i * HH + c], acc);
    g_x[(size_t)n * HH + c] = acc;
}

// ---------------------------------------------------------------------------
// Gather supernode rows of g_x into g_xs
// ---------------------------------------------------------------------------
__global__ void gather_rows_kernel(const int* __restrict__ sup_idx) {
    int s = blockIdx.x;
    int c = threadIdx.x;
    int node = sup_idx[s];
    g_xs[(size_t)s * HH + c] = g_x[(size_t)node * HH + c];
}

// ---------------------------------------------------------------------------
// Weight prep: B[n][k] = W[k][n], split into tf32 hi/lo. grid=192, block=192.
// ---------------------------------------------------------------------------
__global__ void wprep_kernel(const float* __restrict__ W,
                             uint32_t* __restrict__ hi,
                             uint32_t* __restrict__ lo) {
    int n = blockIdx.x, k = threadIdx.x;
    float w = W[k * HH + n];
    uint32_t h = f2tf32(w);
    float l = w - __uint_as_float(h);
    hi[n * HH + k] = h;
    lo[n * HH + k] = f2tf32(l);
}

// ---------------------------------------------------------------------------
// GEMM via mma.sync tf32 (3x split): C[M,192] = A[M,192] @ W + bias
// CTA tile 128(M) x 96(N), BK=32, 256 thr / 8 warps (4Mx2N), warp 32x48.
// B pre-transposed/split as Bth/Btl [n][k].
// ---------------------------------------------------------------------------
#define ASTR 136   // smem A stride (floats), (8k+m)%32 conflict-free
#define BSTR 104   // smem B stride
#define GEMM_SMEM ((2 * 32 * ASTR + 2 * 32 * BSTR) * 4)   // 61440 B

__global__ void __launch_bounds__(256, 2) gemm_mma_kernel(
    const float* __restrict__ A,
    const uint32_t* __restrict__ Bth,
    const uint32_t* __restrict__ Btl,
    const float* __restrict__ bias,
    float* __restrict__ C)
{
    extern __shared__ uint32_t sm[];
    uint32_t* Ah = sm;
    uint32_t* Al = Ah + 32 * ASTR;
    uint32_t* Bh = Al + 32 * ASTR;
    uint32_t* Bl = Bh + 32 * BSTR;

    int tid = threadIdx.x;
    int lane = tid & 31;
    int wid = tid >> 5;
    int m0 = (blockIdx.x >> 1) * 128;
    int n0 = (blockIdx.x & 1) * 96;
    int wm = (wid >> 1) * 32;       // warp M offset in tile
    int wn = (wid & 1) * 48;        // warp N offset in tile
    int r = lane >> 2;              // 0..7
    int q = lane & 3;               // 0..3

    float c[2][6][4];
#pragma unroll
    for (int i = 0; i < 2; i++)
#pragma unroll
        for (int j = 0; j < 6; j++)
#pragma unroll
            for (int k = 0; k < 4; k++) c[i][j][k] = 0.0f;

    for (int kc = 0; kc < 6; kc++) {
        int k0 = kc * 32;
        // ---- stage A tile 128x32 (fp32 -> tf32 hi/lo), transposed to [k][m]
#pragma unroll
        for (int i = 0; i < 4; i++) {
            int idx = tid + 256 * i;          // 0..1023
            int m = idx >> 3, j = idx & 7;
            float4 v = *(const float4*)(A + (size_t)(m0 + m) * HH + k0 + 4 * j);
            uint32_t h0 = f2tf32(v.x), h1 = f2tf32(v.y);
            uint32_t h2 = f2tf32(v.z), h3 = f2tf32(v.w);
            int base = (4 * j) * ASTR + m;
            Ah[base]            = h0;
            Ah[base + ASTR]     = h1;
            Ah[base + 2 * ASTR] = h2;
            Ah[base + 3 * ASTR] = h3;
            Al[base]            = f2tf32(v.x - __uint_as_float(h0));
            Al[base + ASTR]     = f2tf32(v.y - __uint_as_float(h1));
            Al[base + 2 * ASTR] = f2tf32(v.z - __uint_as_float(h2));
            Al[base + 3 * ASTR] = f2tf32(v.w - __uint_as_float(h3));
        }
        // ---- stage B tiles 96x32 (pre-split), transposed to [k][n]
#pragma unroll
        for (int i = 0; i < 3; i++) {
            int idx = tid + 256 * i;          // 0..767
            int n = idx >> 3, j = idx & 7;
            size_t goff = (size_t)(n0 + n) * HH + k0 + 4 * j;
            uint4 vh = *(const uint4*)(Bth + goff);
            uint4 vl = *(const uint4*)(Btl + goff);
            int base = (4 * j) * BSTR + n;
            Bh[base]            = vh.x;
            Bh[base + BSTR]     = vh.y;
            Bh[base + 2 * BSTR] = vh.z;
            Bh[base + 3 * BSTR] = vh.w;
            Bl[base]            = vl.x;
            Bl[base + BSTR]     = vl.y;
            Bl[base + 2 * BSTR] = vl.z;
            Bl[base + 3 * BSTR] = vl.w;
        }
        __syncthreads();

#pragma unroll
        for (int kk = 0; kk < 4; kk++) {
            int ko = kk * 8;
            uint32_t ah[2][4], al[2][4];
#pragma unroll
            for (int mt = 0; mt < 2; mt++) {
                int mb = wm + mt * 16 + r;
                ah[mt][0] = Ah[(ko + q) * ASTR + mb];
                ah[mt][1] = Ah[(ko + q) * ASTR + mb + 8];
                ah[mt][2] = Ah[(ko + q + 4) * ASTR + mb];
                ah[mt][3] = Ah[(ko + q + 4) * ASTR + mb + 8];
                al[mt][0] = Al[(ko + q) * ASTR + mb];
                al[mt][1] = Al[(ko + q) * ASTR + mb + 8];
                al[mt][2] = Al[(ko + q + 4) * ASTR + mb];
                al[mt][3] = Al[(ko + q + 4) * ASTR + mb + 8];
            }
#pragma unroll
            for (int nt = 0; nt < 6; nt++) {
                int nb = wn + nt * 8 + r;
                uint32_t bh0 = Bh[(ko + q) * BSTR + nb];
                uint32_t bh1 = Bh[(ko + q + 4) * BSTR + nb];
                uint32_t bl0 = Bl[(ko + q) * BSTR + nb];
                uint32_t bl1 = Bl[(ko + q + 4) * BSTR + nb];
#pragma unroll
                for (int mt = 0; mt < 2; mt++) {
                    mma_tf32(c[mt][nt], ah[mt][0], ah[mt][1], ah[mt][2], ah[mt][3], bh0, bh1);
                    mma_tf32(c[mt][nt], al[mt][0], al[mt][1], al[mt][2], al[mt][3], bh0, bh1);
                    mma_tf32(c[mt][nt], ah[mt][0], ah[mt][1], ah[mt][2], ah[mt][3], bl0, bl1);
                }
            }
        }
        __syncthreads();
    }

    // ---- epilogue
#pragma unroll
    for (int mt = 0; mt < 2; mt++) {
        int row0 = m0 + wm + mt * 16 + r;
#pragma unroll
        for (int nt = 0; nt < 6; nt++) {
            int col = n0 + wn + nt * 8 + 2 * q;
            float bias0 = 0.0f, bias1 = 0.0f;
            if (bias) { bias0 = bias[col]; bias1 = bias[col + 1]; }
            float2 v0 = make_float2(c[mt][nt][0] + bias0, c[mt][nt][1] + bias1);
            float2 v1 = make_float2(c[mt][nt][2] + bias0, c[mt][nt][3] + bias1);
            *(float2*)(C + (size_t)row0 * HH + col) = v0;
            *(float2*)(C + (size_t)(row0 + 8) * HH + col) = v1;
        }
    }
}

// ---------------------------------------------------------------------------
// K3: pooled GELU. pool[s,c] = mean_e GELU(y[src_e,c] + z[s,c]), fan-in 32.
// ---------------------------------------------------------------------------
__device__ __forceinline__ float gelu_exact(float v) {
    return 0.5f * v * (1.0f + erff(v * 0.70710678118654752f));
}

__global__ void pool_kernel(const int* __restrict__ src_idx) {
    int s = blockIdx.x;
    int c = threadIdx.x;
    __shared__ int srcs[MAXDEG];
    if (c < MAXDEG) srcs[c] = src_idx[s * MAXDEG + c];
    __syncthreads();

    float zc = g_z[(size_t)s * HH + c];
    float acc = 0.0f;
#pragma unroll 4
    for (int e = 0; e < MAXDEG; e++) {
        float v = g_y[(size_t)srcs[e] * HH + c] + zc;
        acc += gelu_exact(v);
    }
    g_pool[(size_t)s * HH + c] = acc * (1.0f / 32.0f);
}

// ---------------------------------------------------------------------------
// launch
// ---------------------------------------------------------------------------
extern "C" void kernel_launch(void* const* d_in, const int* in_sizes, int n_in,
                              void* d_out, int out_size) {
    const float* feat  = (const float*)d_in[0];
    const float* pos   = (const float*)d_in[1];
    const int*   sup   = (const int*)  d_in[2];
    const int*   src   = (const int*)  d_in[4];
    const float* W_in  = (const float*)d_in[6];
    const float* b_in  = (const float*)d_in[7];
    const float* W1    = (const float*)d_in[8];
    const float* b1    = (const float*)d_in[9];
    const float* W2    = (const float*)d_in[10];
    const float* b2    = (const float*)d_in[11];
    float* out = (float*)d_out;

    float *px, *py, *pxs, *pz, *ppool;
    uint32_t *pw1ah, *pw1al, *pw1bh, *pw1bl, *pw2h, *pw2l;
    cudaGetSymbolAddress((void**)&px,    g_x);
    cudaGetSymbolAddress((void**)&py,    g_y);
    cudaGetSymbolAddress((void**)&pxs,   g_xs);
    cudaGetSymbolAddress((void**)&pz,    g_z);
    cudaGetSymbolAddress((void**)&ppool, g_pool);
    cudaGetSymbolAddress((void**)&pw1ah, g_w1a_hi);
    cudaGetSymbolAddress((void**)&pw1al, g_w1a_lo);
    cudaGetSymbolAddress((void**)&pw1bh, g_w1b_hi);
    cudaGetSymbolAddress((void**)&pw1bl, g_w1b_lo);
    cudaGetSymbolAddress((void**)&pw2h,  g_w2_hi);
    cudaGetSymbolAddress((void**)&pw2l,  g_w2_lo);

    cudaFuncSetAttribute(gemm_mma_kernel,
                         cudaFuncAttributeMaxDynamicSharedMemorySize, GEMM_SMEM);

    // 1) node features
    node_embed_kernel<<<NN, HH>>>(feat, pos, W_in, b_in);

    // 2) gather supernode rows + weight prep
    gather_rows_kernel<<<SS, HH>>>(sup);
    wprep_kernel<<<HH, HH>>>(W1, pw1ah, pw1al);
    wprep_kernel<<<HH, HH>>>(W1 + (size_t)HH * HH, pw1bh, pw1bl);
    wprep_kernel<<<HH, HH>>>(W2, pw2h, pw2l);

    // 3) y = x @ W1_top (big GEMM, tensor cores via mma.sync)
    gemm_mma_kernel<<<(NN / 128) * 2, 256, GEMM_SMEM>>>(px, pw1ah, pw1al, nullptr, py);

    // 4) z = x_sup @ W1_bot + b1
    gemm_mma_kernel<<<(SS / 128) * 2, 256, GEMM_SMEM>>>(pxs, pw1bh, pw1bl, b1, pz);

    // 5) pooled GELU activations
    pool_kernel<<<SS, HH>>>(src);

    // 6) out = pool @ W2 + b2
    gemm_mma_kernel<<<(SS / 128) * 2, 256, GEMM_SMEM>>>(ppool, pw2h, pw2l, b2, out);
}

// round 4
// speedup vs baseline: 1.3588x; 1.0524x over previous
#include <cuda_runtime.h>
#include <math.h>
#include <stdint.h>

// Problem constants (fixed by setup_inputs)
#define NN      262144
#define HH      192
#define SS      16384
#define EE      524288
#define IND     16
#define MAXDEG  32

// ---------------- device scratch (no allocation allowed) -------------------
__device__ uint32_t g_xp[(size_t)NN * HH];    // packed bf16 split x: (hi<<16)|lo
__device__ float    g_z[(size_t)SS * HH];     // x_sup @ W1_bot + b1
__device__ float    g_pool[(size_t)SS * HH];  // pooled GELU activations
// packed transposed split weights [n][k]: (hi<<16)|lo
__device__ uint32_t g_w1a[HH * HH];           // W1 top (rows 0..191)
__device__ uint32_t g_w1b[HH * HH];           // W1 bottom (rows 192..383)
__device__ uint32_t g_w2[HH * HH];

// ---------------- helpers ---------------------------------------------------
__device__ __forceinline__ uint16_t f2bf(float x) {
    uint16_t r;
    asm("cvt.rn.bf16.f32 %0, %1;" : "=h"(r) : "f"(x));
    return r;
}
__device__ __forceinline__ uint32_t pack_split(float x) {
    uint16_t h = f2bf(x);
    float hf = __uint_as_float(((uint32_t)h) << 16);
    uint16_t l = f2bf(x - hf);
    return (((uint32_t)h) << 16) | (uint32_t)l;
}

__device__ __forceinline__ void ldm_x4(uint32_t addr, uint32_t r[4]) {
    asm volatile("ldmatrix.sync.aligned.m8n8.x4.shared.b16 {%0,%1,%2,%3}, [%4];"
                 : "=r"(r[0]), "=r"(r[1]), "=r"(r[2]), "=r"(r[3]) : "r"(addr));
}

__device__ __forceinline__ void mma_bf16(float c[4], const uint32_t a[4],
                                         uint32_t b0, uint32_t b1) {
    asm volatile(
        "mma.sync.aligned.m16n8k16.row.col.f32.bf16.bf16.f32 "
        "{%0,%1,%2,%3}, {%4,%5,%6,%7}, {%8,%9}, {%0,%1,%2,%3};"
        : "+f"(c[0]), "+f"(c[1]), "+f"(c[2]), "+f"(c[3])
        : "r"(a[0]), "r"(a[1]), "r"(a[2]), "r"(a[3]), "r"(b0), "r"(b1));
}

__device__ __forceinline__ float gelu_exact(float v) {
    return 0.5f * v * (1.0f + erff(v * 0.70710678118654752f));
}

// ---------------- shared-memory layout for GEMM kernels ---------------------
// A tiles: 128 rows x 32 k (bf16), row stride 80B. B tiles: 192 x 32, same.
#define A_BYTES   (128 * 80)          // 10240
#define B_BYTES   (192 * 80)          // 15360
#define OFF_AH    0
#define OFF_AL    (A_BYTES)
#define OFF_BH    (2 * A_BYTES)
#define OFF_BL    (2 * A_BYTES + B_BYTES)
#define OFF_IDX   (2 * A_BYTES + 2 * B_BYTES)
#define SMEM_SZ   (OFF_IDX + 512)     // 51712

// unpack uint4 of packed (hi|lo) into smem-word pairs
__device__ __forceinline__ void unpack4(uint4 v, uint2& h, uint2& l) {
    h.x = (v.x >> 16) | (v.y & 0xFFFF0000u);
    h.y = (v.z >> 16) | (v.w & 0xFFFF0000u);
    l.x = (v.x & 0xFFFFu) | (v.y << 16);
    l.y = (v.z & 0xFFFFu) | (v.w << 16);
}

// ---------------------------------------------------------------------------
// Shared mainloop: stages A/B split tiles and runs 3-term bf16 MMAs.
// Defined as a macro-free inline via templates.
// ---------------------------------------------------------------------------
template<bool APACKED, bool GATHER>
__device__ __forceinline__ void gemm_mainloop(
    const void* Aany, const uint32_t* __restrict__ Bpk,
    const int* __restrict__ ridx, char* sm, uint32_t sbase,
    float c[2][12][4])
{
    int tid = threadIdx.x;
    int lane = tid & 31;
    int wid = tid >> 5;
    int wm = wid >> 1;
    int wn = (wid & 1) * 96;
    int R0 = wm * 32;

    int* IDX = (int*)(sm + OFF_IDX);
    if (GATHER) {
        if (tid < 128) IDX[tid] = ridx[blockIdx.x * 128 + tid];
        __syncthreads();
    }

#pragma unroll
    for (int mt = 0; mt < 2; mt++)
#pragma unroll
        for (int nt = 0; nt < 12; nt++)
#pragma unroll
            for (int k = 0; k < 4; k++) c[mt][nt][k] = 0.0f;

    // precompute ldmatrix lane addresses (byte offsets into tiles)
    uint32_t a_lrow = (lane & 7) + ((lane >> 3) & 1) * 8;   // row within 16
    uint32_t a_lcol = (lane >> 4) * 16;                     // k-half bytes
    uint32_t b_lrow = (lane & 7) + (lane >> 4) * 8;         // n within 16
    uint32_t b_lcol = ((lane >> 3) & 1) * 16;               // k-half bytes

    for (int kc = 0; kc < 6; kc++) {
        int k0 = kc * 32;
        // ---- stage A: 128 rows x 32 k
#pragma unroll
        for (int i = 0; i < 4; i++) {
            int idx = tid + 256 * i;
            int row = idx >> 3, j = idx & 7;
            int arow = GATHER ? IDX[row] : (blockIdx.x * 128 + row);
            uint2 h, l;
            if (APACKED) {
                uint4 v = *(const uint4*)((const uint32_t*)Aany +
                                          (size_t)arow * HH + k0 + 4 * j);
                unpack4(v, h, l);
            } else {
                float4 f = *(const float4*)((const float*)Aany +
                                            (size_t)arow * HH + k0 + 4 * j);
                uint32_t p0 = pack_split(f.x), p1 = pack_split(f.y);
                uint32_t p2 = pack_split(f.z), p3 = pack_split(f.w);
                unpack4(make_uint4(p0, p1, p2, p3), h, l);
            }
            *(uint2*)(sm + OFF_AH + row * 80 + j * 8) = h;
            *(uint2*)(sm + OFF_AL + row * 80 + j * 8) = l;
        }
        // ---- stage B: 192 rows(n) x 32 k
#pragma unroll
        for (int i = 0; i < 6; i++) {
            int idx = tid + 256 * i;
            int n = idx >> 3, j = idx & 7;
            uint4 v = *(const uint4*)(Bpk + (size_t)n * HH + k0 + 4 * j);
            uint2 h, l;
            unpack4(v, h, l);
            *(uint2*)(sm + OFF_BH + n * 80 + j * 8) = h;
            *(uint2*)(sm + OFF_BL + n * 80 + j * 8) = l;
        }
        __syncthreads();

#pragma unroll
        for (int ks = 0; ks < 2; ks++) {
            uint32_t ah[2][4], al[2][4];
#pragma unroll
            for (int mt = 0; mt < 2; mt++) {
                uint32_t ro = (R0 + mt * 16 + a_lrow) * 80 + ks * 32 + a_lcol;
                ldm_x4(sbase + OFF_AH + ro, ah[mt]);
                ldm_x4(sbase + OFF_AL + ro, al[mt]);
            }
#pragma unroll
            for (int np = 0; np < 6; np++) {
                uint32_t bo = (wn + np * 16 + b_lrow) * 80 + ks * 32 + b_lcol;
                uint32_t bh[4], bl[4];
                ldm_x4(sbase + OFF_BH + bo, bh);
                ldm_x4(sbase + OFF_BL + bo, bl);
#pragma unroll
                for (int mt = 0; mt < 2; mt++) {
                    mma_bf16(c[mt][2 * np],     ah[mt], bh[0], bh[1]);
                    mma_bf16(c[mt][2 * np],     al[mt], bh[0], bh[1]);
                    mma_bf16(c[mt][2 * np],     ah[mt], bl[0], bl[1]);
                    mma_bf16(c[mt][2 * np + 1], ah[mt], bh[2], bh[3]);
                    mma_bf16(c[mt][2 * np + 1], al[mt], bh[2], bh[3]);
                    mma_bf16(c[mt][2 * np + 1], ah[mt], bl[2], bl[3]);
                }
            }
        }
        __syncthreads();
    }
}

// ---------------------------------------------------------------------------
// Plain GEMM: C[M,192] = A @ Wpk (+bias). Optional row gather for A.
// ---------------------------------------------------------------------------
template<bool APACKED, bool GATHER>
__global__ void __launch_bounds__(256) gemm_kernel(
    const void* __restrict__ Aany, const uint32_t* __restrict__ Bpk,
    const int* __restrict__ ridx, const float* __restrict__ bias,
    float* __restrict__ C)
{
    extern __shared__ char sm[];
    uint32_t sbase = (uint32_t)__cvta_generic_to_shared(sm);
    float c[2][12][4];
    gemm_mainloop<APACKED, GATHER>(Aany, Bpk, ridx, sm, sbase, c);

    int lane = threadIdx.x & 31;
    int wid = threadIdx.x >> 5;
    int wm = wid >> 1;
    int wn = (wid & 1) * 96;
    int r = lane >> 2, q = lane & 3;
#pragma unroll
    for (int mt = 0; mt < 2; mt++) {
        int row = blockIdx.x * 128 + wm * 32 + mt * 16 + r;
#pragma unroll
        for (int nt = 0; nt < 12; nt++) {
            int col = wn + nt * 8 + 2 * q;
            float b0 = bias ? bias[col] : 0.0f;
            float b1 = bias ? bias[col + 1] : 0.0f;
            *(float2*)(C + (size_t)row * HH + col) =
                make_float2(c[mt][nt][0] + b0, c[mt][nt][1] + b1);
            *(float2*)(C + (size_t)(row + 8) * HH + col) =
                make_float2(c[mt][nt][2] + b0, c[mt][nt][3] + b1);
        }
    }
}

// ---------------------------------------------------------------------------
// Fused message+pool: h = x[src[e]] @ W1_top + z[s]; GELU; mean over the 32
// edges of each supernode. Warp M-tile (32 rows) == one supernode.
// ---------------------------------------------------------------------------
__global__ void __launch_bounds__(256) fused_msg_pool_kernel(
    const int* __restrict__ src_idx, const uint32_t* __restrict__ W1a)
{
    extern __shared__ char sm[];
    uint32_t sbase = (uint32_t)__cvta_generic_to_shared(sm);
    float c[2][12][4];
    gemm_mainloop<true, true>((const void*)g_xp, W1a, src_idx, sm, sbase, c);

    int lane = threadIdx.x & 31;
    int wid = threadIdx.x >> 5;
    int wm = wid >> 1;
    int wn = (wid & 1) * 96;
    int q = lane & 3;
    int s = blockIdx.x * 4 + wm;

#pragma unroll
    for (int nt = 0; nt < 12; nt++) {
        int col = wn + nt * 8 + 2 * q;
        float2 zv = *(const float2*)(g_z + (size_t)s * HH + col);
        float g0 = gelu_exact(c[0][nt][0] + zv.x) + gelu_exact(c[0][nt][2] + zv.x)
                 + gelu_exact(c[1][nt][0] + zv.x) + gelu_exact(c[1][nt][2] + zv.x);
        float g1 = gelu_exact(c[0][nt][1] + zv.y) + gelu_exact(c[0][nt][3] + zv.y)
                 + gelu_exact(c[1][nt][1] + zv.y) + gelu_exact(c[1][nt][3] + zv.y);
#pragma unroll
        for (int d = 4; d < 32; d <<= 1) {
            g0 += __shfl_xor_sync(0xFFFFFFFFu, g0, d);
            g1 += __shfl_xor_sync(0xFFFFFFFFu, g1, d);
        }
        if (lane < 4)
            *(float2*)(g_pool + (size_t)s * HH + col) =
                make_float2(g0 * (1.0f / 32.0f), g1 * (1.0f / 32.0f));
    }
}

// ---------------------------------------------------------------------------
// K1: x = feat @ W_in + b_in + sincos(pos), stored packed split. 4 nodes/block.
// ---------------------------------------------------------------------------
__global__ void node_embed_kernel(const float* __restrict__ feat,
                                  const float* __restrict__ pos,
                                  const float* __restrict__ W_in,
                                  const float* __restrict__ b_in) {
    int n0 = blockIdx.x * 4;
    int c = threadIdx.x;
    __shared__ float f[4][IND];
    __shared__ float p[4][3];
    if (c < 64) f[c >> 4][c & 15] = feat[(n0 + (c >> 4)) * IND + (c & 15)];
    else if (c < 76) {
        int t = c - 64;
        p[t / 3][t % 3] = pos[(n0 + t / 3) * 3 + t % 3];
    }

    float w[IND];
#pragma unroll
    for (int i = 0; i < IND; i++) w[i] = W_in[i * HH + c];
    float bc = b_in[c];

    int d = c >> 6;
    int t = c & 63;
    int j = t & 31;
    float omega = exp2f(-(float)j * (13.2877123795494f / 32.0f));
    __syncthreads();

#pragma unroll
    for (int nn = 0; nn < 4; nn++) {
        float arg = p[nn][d] * omega;
        float emb = (t < 32) ? sinf(arg) : cosf(arg);
        float acc = bc + emb;
#pragma unroll
        for (int i = 0; i < IND; i++)
            acc = fmaf(f[nn][i], w[i], acc);
        g_xp[(size_t)(n0 + nn) * HH + c] = pack_split(acc);
    }
}

// ---------------------------------------------------------------------------
// Weight prep: packed-split transposed weights [n][k]
// ---------------------------------------------------------------------------
__global__ void wprep_kernel(const float* __restrict__ W,
                             uint32_t* __restrict__ out) {
    int n = blockIdx.x, k = threadIdx.x;
    out[n * HH + k] = pack_split(W[k * HH + n]);
}

// ---------------------------------------------------------------------------
// launch
// ---------------------------------------------------------------------------
extern "C" void kernel_launch(void* const* d_in, const int* in_sizes, int n_in,
                              void* d_out, int out_size) {
    const float* feat  = (const float*)d_in[0];
    const float* pos   = (const float*)d_in[1];
    const int*   sup   = (const int*)  d_in[2];
    const int*   src   = (const int*)  d_in[4];
    const float* W_in  = (const float*)d_in[6];
    const float* b_in  = (const float*)d_in[7];
    const float* W1    = (const float*)d_in[8];
    const float* b1    = (const float*)d_in[9];
    const float* W2    = (const float*)d_in[10];
    const float* b2    = (const float*)d_in[11];
    float* out = (float*)d_out;

    uint32_t *pxp, *pw1a, *pw1b, *pw2;
    float *pz, *ppool;
    cudaGetSymbolAddress((void**)&pxp,   g_xp);
    cudaGetSymbolAddress((void**)&pz,    g_z);
    cudaGetSymbolAddress((void**)&ppool, g_pool);
    cudaGetSymbolAddress((void**)&pw1a,  g_w1a);
    cudaGetSymbolAddress((void**)&pw1b,  g_w1b);
    cudaGetSymbolAddress((void**)&pw2,   g_w2);

    cudaFuncSetAttribute(gemm_kernel<true, true>,
                         cudaFuncAttributeMaxDynamicSharedMemorySize, SMEM_SZ);
    cudaFuncSetAttribute(gemm_kernel<false, false>,
                         cudaFuncAttributeMaxDynamicSharedMemorySize, SMEM_SZ);
    cudaFuncSetAttribute(fused_msg_pool_kernel,
                         cudaFuncAttributeMaxDynamicSharedMemorySize, SMEM_SZ);

    // weight prep + node embed
    wprep_kernel<<<HH, HH>>>(W1, pw1a);
    wprep_kernel<<<HH, HH>>>(W1 + (size_t)HH * HH, pw1b);
    wprep_kernel<<<HH, HH>>>(W2, pw2);
    node_embed_kernel<<<NN / 4, HH>>>(feat, pos, W_in, b_in);

    // z = x[sup] @ W1_bot + b1   (gathered, packed A)
    gemm_kernel<true, true><<<SS / 128, 256, SMEM_SZ>>>(
        (const void*)pxp, pw1b, sup, b1, pz);

    // fused: pool[s] = mean_e GELU(x[src[e]] @ W1_top + z[s])
    fused_msg_pool_kernel<<<EE / 128, 256, SMEM_SZ>>>(src, pw1a);

    // out = pool @ W2 + b2   (fp32 A, no gather)
    gemm_kernel<false, false><<<SS / 128, 256, SMEM_SZ>>>(
        (const void*)ppool, pw2, nullptr, b2, out);
}

// round 5
// speedup vs baseline: 2.8550x; 2.1011x over previous
#include <cuda_runtime.h>
#include <math.h>
#include <stdint.h>

// Problem constants (fixed by setup_inputs)
#define NN      262144
#define HH      192
#define SS      16384
#define EE      524288
#define IND     16
#define MAXDEG  32

// ---------------- device scratch (no allocation allowed) -------------------
__device__ uint16_t g_xh[(size_t)NN * HH];   // bf16 hi of x
__device__ uint16_t g_xl[(size_t)NN * HH];   // bf16 lo of x
__device__ float    g_y[(size_t)NN * HH];    // x @ W1_top (fp32)
__device__ float    g_z[(size_t)SS * HH];    // x_sup @ W1_bot + b1
__device__ uint16_t g_ph[(size_t)SS * HH];   // pooled GELU, bf16 hi
__device__ uint16_t g_pl[(size_t)SS * HH];   // pooled GELU, bf16 lo
// transposed split weights [n][k], bf16
__device__ uint16_t g_w1a_h[HH * HH], g_w1a_l[HH * HH];
__device__ uint16_t g_w1b_h[HH * HH], g_w1b_l[HH * HH];
__device__ uint16_t g_w2_h[HH * HH],  g_w2_l[HH * HH];

// ---------------- helpers ---------------------------------------------------
__device__ __forceinline__ uint16_t f2bf(float x) {
    uint16_t r;
    asm("cvt.rn.bf16.f32 %0, %1;" : "=h"(r) : "f"(x));
    return r;
}
__device__ __forceinline__ void split_bf16(float x, uint16_t& h, uint16_t& l) {
    h = f2bf(x);
    float hf = __uint_as_float(((uint32_t)h) << 16);
    l = f2bf(x - hf);
}

__device__ __forceinline__ void cp16(uint32_t s, const void* g) {
    asm volatile("cp.async.cg.shared.global [%0], [%1], 16;"
                 :: "r"(s), "l"(g));
}
__device__ __forceinline__ void cp_commit() {
    asm volatile("cp.async.commit_group;" ::: "memory");
}
template<int N>
__device__ __forceinline__ void cp_wait() {
    asm volatile("cp.async.wait_group %0;" :: "n"(N) : "memory");
}

__device__ __forceinline__ void ldm_x4(uint32_t addr, uint32_t r[4]) {
    asm volatile("ldmatrix.sync.aligned.m8n8.x4.shared.b16 {%0,%1,%2,%3}, [%4];"
                 : "=r"(r[0]), "=r"(r[1]), "=r"(r[2]), "=r"(r[3]) : "r"(addr));
}

__device__ __forceinline__ void mma_bf16(float c[4], const uint32_t a[4],
                                         uint32_t b0, uint32_t b1) {
    asm volatile(
        "mma.sync.aligned.m16n8k16.row.col.f32.bf16.bf16.f32 "
        "{%0,%1,%2,%3}, {%4,%5,%6,%7}, {%8,%9}, {%0,%1,%2,%3};"
        : "+f"(c[0]), "+f"(c[1]), "+f"(c[2]), "+f"(c[3])
        : "r"(a[0]), "r"(a[1]), "r"(a[2]), "r"(a[3]), "r"(b0), "r"(b1));
}

__device__ __forceinline__ float gelu_exact(float v) {
    return 0.5f * v * (1.0f + erff(v * 0.70710678118654752f));
}

// ---------------- GEMM shared-memory layout ---------------------------------
// Per buffer: A hi 128x32 bf16 (80B rows) | A lo | B hi 96x32 | B lo
#define BUF_AH  0
#define BUF_AL  10240
#define BUF_BH  20480
#define BUF_BL  28160
#define BUF_SZ  35840
#define OFF_IDX (2 * BUF_SZ)          // 71680
#define SMEM_SZ (OFF_IDX + 512)       // 72192

template<bool GATHER>
__device__ __forceinline__ void stage_tiles(
    int kc, int buf, int tid, int m0, int n0,
    const uint16_t* __restrict__ Ah, const uint16_t* __restrict__ Al,
    const uint16_t* __restrict__ Bh, const uint16_t* __restrict__ Bl,
    const int* __restrict__ IDX, uint32_t sbase)
{
    int k0 = kc * 32;
    uint32_t sb = sbase + buf * BUF_SZ;
    // A: 128 rows x 32 k, 4 x 16B chunks per row (hi & lo)
#pragma unroll
    for (int i = 0; i < 2; i++) {
        int id = tid + 256 * i;
        int row = id >> 2, j = id & 3;
        int ar = GATHER ? IDX[row] : (m0 + row);
        size_t go = (size_t)ar * HH + k0 + j * 8;
        uint32_t sa = sb + BUF_AH + row * 80 + j * 16;
        cp16(sa, Ah + go);
        cp16(sa + (BUF_AL - BUF_AH), Al + go);
    }
    // B: 96 rows x 32 k
#pragma unroll
    for (int i = 0; i < 2; i++) {
        int id = tid + 256 * i;
        if (id < 384) {
            int row = id >> 2, j = id & 3;
            size_t go = (size_t)(n0 + row) * HH + k0 + j * 8;
            uint32_t sa = sb + BUF_BH + row * 80 + j * 16;
            cp16(sa, Bh + go);
            cp16(sa + (BUF_BL - BUF_BH), Bl + go);
        }
    }
}

// ---------------------------------------------------------------------------
// GEMM: C[M,192] = A @ W (+bias), split-bf16 3-term, double-buffered cp.async.
// CTA tile 128(M) x 96(N); grid.x = Mtiles*2 (N halves). Optional row gather.
// ---------------------------------------------------------------------------
template<bool GATHER>
__global__ void __launch_bounds__(256, 2) gemm_kernel(
    const uint16_t* __restrict__ Ah, const uint16_t* __restrict__ Al,
    const uint16_t* __restrict__ Bh, const uint16_t* __restrict__ Bl,
    const int* __restrict__ ridx, const float* __restrict__ bias,
    float* __restrict__ C)
{
    extern __shared__ char sm[];
    uint32_t sbase = (uint32_t)__cvta_generic_to_shared(sm);
    int tid = threadIdx.x;
    int lane = tid & 31;
    int wid = tid >> 5;
    int mtile = blockIdx.x >> 1;
    int n0 = (blockIdx.x & 1) * 96;
    int m0 = mtile * 128;
    int* IDX = (int*)(sm + OFF_IDX);

    if (GATHER) {
        if (tid < 128) IDX[tid] = ridx[m0 + tid];
        __syncthreads();
    }

    float c[2][6][4];
#pragma unroll
    for (int mt = 0; mt < 2; mt++)
#pragma unroll
        for (int nt = 0; nt < 6; nt++)
#pragma unroll
            for (int k = 0; k < 4; k++) c[mt][nt][k] = 0.0f;

    int wm = wid >> 1;              // 0..3 (M quadrant of 32)
    int wn = (wid & 1) * 48;        // N half within 96
    uint32_t a_lrow = (lane & 7) + ((lane >> 3) & 1) * 8;
    uint32_t a_lcol = (lane >> 4) * 16;
    uint32_t b_lrow = (lane & 7) + (lane >> 4) * 8;
    uint32_t b_lcol = ((lane >> 3) & 1) * 16;

    stage_tiles<GATHER>(0, 0, tid, m0, n0, Ah, Al, Bh, Bl, IDX, sbase);
    cp_commit();

    for (int kc = 0; kc < 6; kc++) {
        if (kc < 5) {
            stage_tiles<GATHER>(kc + 1, (kc + 1) & 1, tid, m0, n0,
                                Ah, Al, Bh, Bl, IDX, sbase);
            cp_commit();
            cp_wait<1>();
        } else {
            cp_wait<0>();
        }
        __syncthreads();

        uint32_t sb = sbase + (kc & 1) * BUF_SZ;
#pragma unroll
        for (int ks = 0; ks < 2; ks++) {
            uint32_t ah[2][4], al[2][4];
#pragma unroll
            for (int mt = 0; mt < 2; mt++) {
                uint32_t ro = (wm * 32 + mt * 16 + a_lrow) * 80 + ks * 32 + a_lcol;
                ldm_x4(sb + BUF_AH + ro, ah[mt]);
                ldm_x4(sb + BUF_AL + ro, al[mt]);
            }
#pragma unroll
            for (int np = 0; np < 3; np++) {
                uint32_t bo = (wn + np * 16 + b_lrow) * 80 + ks * 32 + b_lcol;
                uint32_t bh[4], bl[4];
                ldm_x4(sb + BUF_BH + bo, bh);
                ldm_x4(sb + BUF_BL + bo, bl);
#pragma unroll
                for (int mt = 0; mt < 2; mt++) {
                    mma_bf16(c[mt][2 * np],     ah[mt], bh[0], bh[1]);
                    mma_bf16(c[mt][2 * np],     al[mt], bh[0], bh[1]);
                    mma_bf16(c[mt][2 * np],     ah[mt], bl[0], bl[1]);
                    mma_bf16(c[mt][2 * np + 1], ah[mt], bh[2], bh[3]);
                    mma_bf16(c[mt][2 * np + 1], al[mt], bh[2], bh[3]);
                    mma_bf16(c[mt][2 * np + 1], ah[mt], bl[2], bl[3]);
                }
            }
        }
        __syncthreads();
    }

    // epilogue
    int r = lane >> 2, q = lane & 3;
#pragma unroll
    for (int mt = 0; mt < 2; mt++) {
        int row = m0 + wm * 32 + mt * 16 + r;
#pragma unroll
        for (int nt = 0; nt < 6; nt++) {
            int col = n0 + wn + nt * 8 + 2 * q;
            float b0 = bias ? bias[col] : 0.0f;
            float b1 = bias ? bias[col + 1] : 0.0f;
            *(float2*)(C + (size_t)row * HH + col) =
                make_float2(c[mt][nt][0] + b0, c[mt][nt][1] + b1);
            *(float2*)(C + (size_t)(row + 8) * HH + col) =
                make_float2(c[mt][nt][2] + b0, c[mt][nt][3] + b1);
        }
    }
}

// ---------------------------------------------------------------------------
// K1: x = feat @ W_in + b_in + sincos(pos); store split bf16. 16 nodes/block.
// ---------------------------------------------------------------------------
__global__ void node_embed_kernel(const float* __restrict__ feat,
                                  const float* __restrict__ pos,
                                  const float* __restrict__ W_in,
                                  const float* __restrict__ b_in) {
    int n0 = blockIdx.x * 16;
    int c = threadIdx.x;
    __shared__ __align__(16) float f[16][IND];
    __shared__ float p[16][3];
    for (int id = c; id < 16 * IND; id += HH)
        f[id >> 4][id & 15] = feat[(n0 + (id >> 4)) * IND + (id & 15)];
    if (c < 48) p[c / 3][c % 3] = pos[(n0 + c / 3) * 3 + c % 3];

    float w[IND];
#pragma unroll
    for (int i = 0; i < IND; i++) w[i] = W_in[i * HH + c];
    float bc = b_in[c];

    int d = c >> 6;
    int t = c & 63;
    int j = t & 31;
    float omega = exp2f(-(float)j * (13.2877123795494f / 32.0f));
    __syncthreads();

#pragma unroll 4
    for (int nn = 0; nn < 16; nn++) {
        float arg = p[nn][d] * omega;
        float emb = (t < 32) ? sinf(arg) : cosf(arg);
        float acc = bc + emb;
#pragma unroll
        for (int i4 = 0; i4 < 4; i4++) {
            float4 v = *(const float4*)&f[nn][4 * i4];
            acc = fmaf(v.x, w[4 * i4 + 0], acc);
            acc = fmaf(v.y, w[4 * i4 + 1], acc);
            acc = fmaf(v.z, w[4 * i4 + 2], acc);
            acc = fmaf(v.w, w[4 * i4 + 3], acc);
        }
        uint16_t h, l;
        split_bf16(acc, h, l);
        g_xh[(size_t)(n0 + nn) * HH + c] = h;
        g_xl[(size_t)(n0 + nn) * HH + c] = l;
    }
}

// ---------------------------------------------------------------------------
// Weight prep: transposed split [n][k]
// ---------------------------------------------------------------------------
__global__ void wprep_kernel(const float* __restrict__ W,
                             uint16_t* __restrict__ oh,
                             uint16_t* __restrict__ ol) {
    int n = blockIdx.x, k = threadIdx.x;
    uint16_t h, l;
    split_bf16(W[k * HH + n], h, l);
    oh[n * HH + k] = h;
    ol[n * HH + k] = l;
}

// ---------------------------------------------------------------------------
// Pool: pool[s,c] = mean_e GELU(y[src_e,c] + z[s,c]); store split bf16.
// ---------------------------------------------------------------------------
__global__ void pool_kernel(const int* __restrict__ src_idx) {
    int s = blockIdx.x;
    int c = threadIdx.x;
    __shared__ int srcs[MAXDEG];
    if (c < MAXDEG) srcs[c] = src_idx[s * MAXDEG + c];
    __syncthreads();

    float zc = g_z[(size_t)s * HH + c];
    float acc = 0.0f;
#pragma unroll 4
    for (int e = 0; e < MAXDEG; e++) {
        float v = g_y[(size_t)srcs[e] * HH + c] + zc;
        acc += gelu_exact(v);
    }
    acc *= (1.0f / 32.0f);
    uint16_t h, l;
    split_bf16(acc, h, l);
    g_ph[(size_t)s * HH + c] = h;
    g_pl[(size_t)s * HH + c] = l;
}

// ---------------------------------------------------------------------------
// launch
// ---------------------------------------------------------------------------
extern "C" void kernel_launch(void* const* d_in, const int* in_sizes, int n_in,
                              void* d_out, int out_size) {
    const float* feat  = (const float*)d_in[0];
    const float* pos   = (const float*)d_in[1];
    const int*   sup   = (const int*)  d_in[2];
    const int*   src   = (const int*)  d_in[4];
    const float* W_in  = (const float*)d_in[6];
    const float* b_in  = (const float*)d_in[7];
    const float* W1    = (const float*)d_in[8];
    const float* b1    = (const float*)d_in[9];
    const float* W2    = (const float*)d_in[10];
    const float* b2    = (const float*)d_in[11];
    float* out = (float*)d_out;

    uint16_t *pxh, *pxl, *pph, *ppl;
    uint16_t *pw1ah, *pw1al, *pw1bh, *pw1bl, *pw2h, *pw2l;
    float *py, *pz;
    cudaGetSymbolAddress((void**)&pxh,   g_xh);
    cudaGetSymbolAddress((void**)&pxl,   g_xl);
    cudaGetSymbolAddress((void**)&py,    g_y);
    cudaGetSymbolAddress((void**)&pz,    g_z);
    cudaGetSymbolAddress((void**)&pph,   g_ph);
    cudaGetSymbolAddress((void**)&ppl,   g_pl);
    cudaGetSymbolAddress((void**)&pw1ah, g_w1a_h);
    cudaGetSymbolAddress((void**)&pw1al, g_w1a_l);
    cudaGetSymbolAddress((void**)&pw1bh, g_w1b_h);
    cudaGetSymbolAddress((void**)&pw1bl, g_w1b_l);
    cudaGetSymbolAddress((void**)&pw2h,  g_w2_h);
    cudaGetSymbolAddress((void**)&pw2l,  g_w2_l);

    cudaFuncSetAttribute(gemm_kernel<true>,
                         cudaFuncAttributeMaxDynamicSharedMemorySize, SMEM_SZ);
    cudaFuncSetAttribute(gemm_kernel<false>,
                         cudaFuncAttributeMaxDynamicSharedMemorySize, SMEM_SZ);

    // weight prep + node embed
    wprep_kernel<<<HH, HH>>>(W1, pw1ah, pw1al);
    wprep_kernel<<<HH, HH>>>(W1 + (size_t)HH * HH, pw1bh, pw1bl);
    wprep_kernel<<<HH, HH>>>(W2, pw2h, pw2l);
    node_embed_kernel<<<NN / 16, HH>>>(feat, pos, W_in, b_in);

    // z = x[sup] @ W1_bot + b1
    gemm_kernel<true><<<(SS / 128) * 2, 256, SMEM_SZ>>>(
        pxh, pxl, pw1bh, pw1bl, sup, b1, pz);

    // y = x @ W1_top (big GEMM)
    gemm_kernel<false><<<(NN / 128) * 2, 256, SMEM_SZ>>>(
        pxh, pxl, pw1ah, pw1al, nullptr, nullptr, py);

    // pool[s] = mean_e GELU(y[src_e] + z[s])
    pool_kernel<<<SS, HH>>>(src);

    // out = pool @ W2 + b2
    gemm_kernel<false><<<(SS / 128) * 2, 256, SMEM_SZ>>>(
        pph, ppl, pw2h, pw2l, nullptr, b2, out);
}

// round 6
// speedup vs baseline: 3.4253x; 1.1998x over previous
#include <cuda_runtime.h>
#include <math.h>
#include <stdint.h>

// Problem constants (fixed by setup_inputs)
#define NN      262144
#define HH      192
#define SS      16384
#define EE      524288
#define IND     16
#define MAXDEG  32

// ---------------- device scratch (no allocation allowed) -------------------
__device__ uint16_t g_xh[(size_t)NN * HH];   // bf16 hi of x
__device__ uint16_t g_xl[(size_t)NN * HH];   // bf16 lo of x
__device__ float    g_y[(size_t)NN * HH];    // x @ W1_top (fp32)
__device__ float    g_z[(size_t)SS * HH];    // x_sup @ W1_bot + b1
__device__ uint16_t g_ph[(size_t)SS * HH];   // pooled GELU, bf16 hi
__device__ uint16_t g_pl[(size_t)SS * HH];   // pooled GELU, bf16 lo
// transposed split weights [n][k], bf16
__device__ uint16_t g_w1a_h[HH * HH], g_w1a_l[HH * HH];
__device__ uint16_t g_w1b_h[HH * HH], g_w1b_l[HH * HH];
__device__ uint16_t g_w2_h[HH * HH],  g_w2_l[HH * HH];

// ---------------- helpers ---------------------------------------------------
__device__ __forceinline__ uint16_t f2bf(float x) {
    uint16_t r;
    asm("cvt.rn.bf16.f32 %0, %1;" : "=h"(r) : "f"(x));
    return r;
}
__device__ __forceinline__ void split_bf16(float x, uint16_t& h, uint16_t& l) {
    h = f2bf(x);
    float hf = __uint_as_float(((uint32_t)h) << 16);
    l = f2bf(x - hf);
}

__device__ __forceinline__ void cp16(uint32_t s, const void* g) {
    asm volatile("cp.async.cg.shared.global [%0], [%1], 16;"
                 :: "r"(s), "l"(g));
}
__device__ __forceinline__ void cp_commit() {
    asm volatile("cp.async.commit_group;" ::: "memory");
}
template<int N>
__device__ __forceinline__ void cp_wait() {
    asm volatile("cp.async.wait_group %0;" :: "n"(N) : "memory");
}

__device__ __forceinline__ void ldm_x4(uint32_t addr, uint32_t r[4]) {
    asm volatile("ldmatrix.sync.aligned.m8n8.x4.shared.b16 {%0,%1,%2,%3}, [%4];"
                 : "=r"(r[0]), "=r"(r[1]), "=r"(r[2]), "=r"(r[3]) : "r"(addr));
}

__device__ __forceinline__ void mma_bf16(float c[4], const uint32_t a[4],
                                         uint32_t b0, uint32_t b1) {
    asm volatile(
        "mma.sync.aligned.m16n8k16.row.col.f32.bf16.bf16.f32 "
        "{%0,%1,%2,%3}, {%4,%5,%6,%7}, {%8,%9}, {%0,%1,%2,%3};"
        : "+f"(c[0]), "+f"(c[1]), "+f"(c[2]), "+f"(c[3])
        : "r"(a[0]), "r"(a[1]), "r"(a[2]), "r"(a[3]), "r"(b0), "r"(b1));
}

__device__ __forceinline__ float gelu_exact(float v) {
    return 0.5f * v * (1.0f + erff(v * 0.70710678118654752f));
}

// ---------------- GEMM shared-memory layout ---------------------------------
// Per buffer: A hi 128x32 bf16 (80B rows) | A lo | B hi 96x32 | B lo
#define BUF_AH  0
#define BUF_AL  10240
#define BUF_BH  20480
#define BUF_BL  28160
#define BUF_SZ  35840
#define NBUF    3
#define OFF_IDX (NBUF * BUF_SZ)       // 107520
#define SMEM_SZ (OFF_IDX + 512)       // 108032

template<bool GATHER>
__device__ __forceinline__ void stage_tiles(
    int kc, int buf, int tid, int m0, int n0,
    const uint16_t* __restrict__ Ah, const uint16_t* __restrict__ Al,
    const uint16_t* __restrict__ Bh, const uint16_t* __restrict__ Bl,
    const int* __restrict__ IDX, uint32_t sbase)
{
    int k0 = kc * 32;
    uint32_t sb = sbase + buf * BUF_SZ;
    // A: 128 rows x 32 k, 4 x 16B chunks per row (hi & lo)
#pragma unroll
    for (int i = 0; i < 2; i++) {
        int id = tid + 256 * i;
        int row = id >> 2, j = id & 3;
        int ar = GATHER ? IDX[row] : (m0 + row);
        size_t go = (size_t)ar * HH + k0 + j * 8;
        uint32_t sa = sb + BUF_AH + row * 80 + j * 16;
        cp16(sa, Ah + go);
        cp16(sa + (BUF_AL - BUF_AH), Al + go);
    }
    // B: 96 rows x 32 k
#pragma unroll
    for (int i = 0; i < 2; i++) {
        int id = tid + 256 * i;
        if (id < 384) {
            int row = id >> 2, j = id & 3;
            size_t go = (size_t)(n0 + row) * HH + k0 + j * 8;
            uint32_t sa = sb + BUF_BH + row * 80 + j * 16;
            cp16(sa, Bh + go);
            cp16(sa + (BUF_BL - BUF_BH), Bl + go);
        }
    }
}

// ---------------------------------------------------------------------------
// GEMM: C[M,192] = A @ W (+bias), split-bf16 3-term, 3-stage cp.async pipeline.
// CTA tile 128(M) x 96(N); grid.x = Mtiles*2 (N halves). Optional row gather.
// ---------------------------------------------------------------------------
template<bool GATHER>
__global__ void __launch_bounds__(256, 2) gemm_kernel(
    const uint16_t* __restrict__ Ah, const uint16_t* __restrict__ Al,
    const uint16_t* __restrict__ Bh, const uint16_t* __restrict__ Bl,
    const int* __restrict__ ridx, const float* __restrict__ bias,
    float* __restrict__ C)
{
    extern __shared__ char sm[];
    uint32_t sbase = (uint32_t)__cvta_generic_to_shared(sm);
    int tid = threadIdx.x;
    int lane = tid & 31;
    int wid = tid >> 5;
    int mtile = blockIdx.x >> 1;
    int n0 = (blockIdx.x & 1) * 96;
    int m0 = mtile * 128;
    int* IDX = (int*)(sm + OFF_IDX);

    if (GATHER) {
        if (tid < 128) IDX[tid] = ridx[m0 + tid];
        __syncthreads();
    }

    float c[2][6][4];
#pragma unroll
    for (int mt = 0; mt < 2; mt++)
#pragma unroll
        for (int nt = 0; nt < 6; nt++)
#pragma unroll
            for (int k = 0; k < 4; k++) c[mt][nt][k] = 0.0f;

    int wm = wid >> 1;              // 0..3 (M quadrant of 32)
    int wn = (wid & 1) * 48;        // N half within 96
    uint32_t a_lrow = (lane & 7) + ((lane >> 3) & 1) * 8;
    uint32_t a_lcol = (lane >> 4) * 16;
    uint32_t b_lrow = (lane & 7) + (lane >> 4) * 8;
    uint32_t b_lcol = ((lane >> 3) & 1) * 16;

    stage_tiles<GATHER>(0, 0, tid, m0, n0, Ah, Al, Bh, Bl, IDX, sbase);
    cp_commit();
    stage_tiles<GATHER>(1, 1, tid, m0, n0, Ah, Al, Bh, Bl, IDX, sbase);
    cp_commit();

    for (int kc = 0; kc < 6; kc++) {
        if (kc < 5) cp_wait<1>(); else cp_wait<0>();
        __syncthreads();
        if (kc < 4) {
            stage_tiles<GATHER>(kc + 2, (kc + 2) % NBUF, tid, m0, n0,
                                Ah, Al, Bh, Bl, IDX, sbase);
            cp_commit();
        }

        uint32_t sb = sbase + (kc % NBUF) * BUF_SZ;
#pragma unroll
        for (int ks = 0; ks < 2; ks++) {
            uint32_t ah[2][4], al[2][4];
#pragma unroll
            for (int mt = 0; mt < 2; mt++) {
                uint32_t ro = (wm * 32 + mt * 16 + a_lrow) * 80 + ks * 32 + a_lcol;
                ldm_x4(sb + BUF_AH + ro, ah[mt]);
                ldm_x4(sb + BUF_AL + ro, al[mt]);
            }
#pragma unroll
            for (int np = 0; np < 3; np++) {
                uint32_t bo = (wn + np * 16 + b_lrow) * 80 + ks * 32 + b_lcol;
                uint32_t bh[4], bl[4];
                ldm_x4(sb + BUF_BH + bo, bh);
                ldm_x4(sb + BUF_BL + bo, bl);
#pragma unroll
                for (int mt = 0; mt < 2; mt++) {
                    mma_bf16(c[mt][2 * np],     ah[mt], bh[0], bh[1]);
                    mma_bf16(c[mt][2 * np],     al[mt], bh[0], bh[1]);
                    mma_bf16(c[mt][2 * np],     ah[mt], bl[0], bl[1]);
                    mma_bf16(c[mt][2 * np + 1], ah[mt], bh[2], bh[3]);
                    mma_bf16(c[mt][2 * np + 1], al[mt], bh[2], bh[3]);
                    mma_bf16(c[mt][2 * np + 1], ah[mt], bl[2], bl[3]);
                }
            }
        }
    }

    // epilogue
    int r = lane >> 2, q = lane & 3;
#pragma unroll
    for (int mt = 0; mt < 2; mt++) {
        int row = m0 + wm * 32 + mt * 16 + r;
#pragma unroll
        for (int nt = 0; nt < 6; nt++) {
            int col = n0 + wn + nt * 8 + 2 * q;
            float b0 = bias ? bias[col] : 0.0f;
            float b1 = bias ? bias[col + 1] : 0.0f;
            *(float2*)(C + (size_t)row * HH + col) =
                make_float2(c[mt][nt][0] + b0, c[mt][nt][1] + b1);
            *(float2*)(C + (size_t)(row + 8) * HH + col) =
                make_float2(c[mt][nt][2] + b0, c[mt][nt][3] + b1);
        }
    }
}

// ---------------------------------------------------------------------------
// K1: x = feat @ W_in + b_in + sincos(pos); split bf16, packed stores.
// 192 threads; thread owns channel pair (2q, 2q+1); 16 nodes/block.
// ---------------------------------------------------------------------------
__global__ void node_embed_kernel(const float* __restrict__ feat,
                                  const float* __restrict__ pos,
                                  const float* __restrict__ W_in,
                                  const float* __restrict__ b_in) {
    int n0 = blockIdx.x * 16;
    int tid = threadIdx.x;
    int half = tid / 96;          // which node of the pair this iteration
    int q = tid % 96;
    int c = 2 * q;

    __shared__ float f[16][IND];
    __shared__ float p[16][3];
    if (tid < 128) {
        f[tid >> 4][tid & 15] = feat[(n0 + (tid >> 4)) * IND + (tid & 15)];
        int id2 = tid + 128;      // second half of feat
        f[id2 >> 4][id2 & 15] = feat[(n0 + (id2 >> 4)) * IND + (id2 & 15)];
    }
    if (tid < 48) p[tid / 3][tid % 3] = pos[(n0 + tid / 3) * 3 + tid % 3];

    float w0[IND], w1[IND];
#pragma unroll
    for (int i = 0; i < IND; i++) {
        w0[i] = W_in[i * HH + c];
        w1[i] = W_in[i * HH + c + 1];
    }
    float b0 = b_in[c], b1 = b_in[c + 1];

    int d = c >> 6;
    int t = c & 63;               // even -> pair never straddles sin/cos
    int j = t & 31;
    float om0 = exp2f(-(float)j * (13.2877123795494f / 32.0f));
    float om1 = exp2f(-(float)(j + 1) * (13.2877123795494f / 32.0f));
    bool issin = (t < 32);
    __syncthreads();

#pragma unroll 2
    for (int nn = half; nn < 16; nn += 2) {
        float pd = p[nn][d];
        float a0 = pd * om0, a1 = pd * om1;
        float e0 = issin ? __sinf(a0) : __cosf(a0);
        float e1 = issin ? __sinf(a1) : __cosf(a1);
        float acc0 = b0 + e0, acc1 = b1 + e1;
#pragma unroll
        for (int i = 0; i < IND; i++) {
            float fv = f[nn][i];
            acc0 = fmaf(fv, w0[i], acc0);
            acc1 = fmaf(fv, w1[i], acc1);
        }
        uint16_t h0, l0, h1, l1;
        split_bf16(acc0, h0, l0);
        split_bf16(acc1, h1, l1);
        size_t o = (size_t)(n0 + nn) * HH + c;
        *(uint32_t*)(g_xh + o) = (uint32_t)h0 | ((uint32_t)h1 << 16);
        *(uint32_t*)(g_xl + o) = (uint32_t)l0 | ((uint32_t)l1 << 16);
    }
}

// ---------------------------------------------------------------------------
// Weight prep: transposed split [n][k]
// ---------------------------------------------------------------------------
__global__ void wprep_kernel(const float* __restrict__ W,
                             uint16_t* __restrict__ oh,
                             uint16_t* __restrict__ ol) {
    int n = blockIdx.x, k = threadIdx.x;
    uint16_t h, l;
    split_bf16(W[k * HH + n], h, l);
    oh[n * HH + k] = h;
    ol[n * HH + k] = l;
}

// ---------------------------------------------------------------------------
// Pool: pool[s,c] = mean_e GELU(y[src_e,c] + z[s,c]); split bf16 output.
// 192 threads = 4 supernodes x 48 threads; 4 channels (float4) per thread.
// ---------------------------------------------------------------------------
__global__ void pool_kernel(const int* __restrict__ src_idx) {
    int tid = threadIdx.x;
    int sgrp = tid / 48;          // 0..3
    int t = tid % 48;
    int s = blockIdx.x * 4 + sgrp;
    int c = t * 4;

    __shared__ int srcs[4][MAXDEG];
    if (tid < 128) srcs[tid >> 5][tid & 31] = src_idx[blockIdx.x * 128 + tid];
    __syncthreads();

    float4 z = *(const float4*)(g_z + (size_t)s * HH + c);
    float4 acc = make_float4(0.f, 0.f, 0.f, 0.f);
#pragma unroll 4
    for (int e = 0; e < MAXDEG; e++) {
        const float4 v = *(const float4*)(g_y + (size_t)srcs[sgrp][e] * HH + c);
        acc.x += gelu_exact(v.x + z.x);
        acc.y += gelu_exact(v.y + z.y);
        acc.z += gelu_exact(v.z + z.z);
        acc.w += gelu_exact(v.w + z.w);
    }
    const float inv = 1.0f / 32.0f;
    uint16_t h[4], l[4];
    split_bf16(acc.x * inv, h[0], l[0]);
    split_bf16(acc.y * inv, h[1], l[1]);
    split_bf16(acc.z * inv, h[2], l[2]);
    split_bf16(acc.w * inv, h[3], l[3]);
    size_t o = (size_t)s * HH + c;
    *(uint2*)(g_ph + o) = make_uint2((uint32_t)h[0] | ((uint32_t)h[1] << 16),
                                     (uint32_t)h[2] | ((uint32_t)h[3] << 16));
    *(uint2*)(g_pl + o) = make_uint2((uint32_t)l[0] | ((uint32_t)l[1] << 16),
                                     (uint32_t)l[2] | ((uint32_t)l[3] << 16));
}

// ---------------------------------------------------------------------------
// launch
// ---------------------------------------------------------------------------
extern "C" void kernel_launch(void* const* d_in, const int* in_sizes, int n_in,
                              void* d_out, int out_size) {
    const float* feat  = (const float*)d_in[0];
    const float* pos   = (const float*)d_in[1];
    const int*   sup   = (const int*)  d_in[2];
    const int*   src   = (const int*)  d_in[4];
    const float* W_in  = (const float*)d_in[6];
    const float* b_in  = (const float*)d_in[7];
    const float* W1    = (const float*)d_in[8];
    const float* b1    = (const float*)d_in[9];
    const float* W2    = (const float*)d_in[10];
    const float* b2    = (const float*)d_in[11];
    float* out = (float*)d_out;

    uint16_t *pxh, *pxl, *pph, *ppl;
    uint16_t *pw1ah, *pw1al, *pw1bh, *pw1bl, *pw2h, *pw2l;
    float *py, *pz;
    cudaGetSymbolAddress((void**)&pxh,   g_xh);
    cudaGetSymbolAddress((void**)&pxl,   g_xl);
    cudaGetSymbolAddress((void**)&py,    g_y);
    cudaGetSymbolAddress((void**)&pz,    g_z);
    cudaGetSymbolAddress((void**)&pph,   g_ph);
    cudaGetSymbolAddress((void**)&ppl,   g_pl);
    cudaGetSymbolAddress((void**)&pw1ah, g_w1a_h);
    cudaGetSymbolAddress((void**)&pw1al, g_w1a_l);
    cudaGetSymbolAddress((void**)&pw1bh, g_w1b_h);
    cudaGetSymbolAddress((void**)&pw1bl, g_w1b_l);
    cudaGetSymbolAddress((void**)&pw2h,  g_w2_h);
    cudaGetSymbolAddress((void**)&pw2l,  g_w2_l);

    cudaFuncSetAttribute(gemm_kernel<true>,
                         cudaFuncAttributeMaxDynamicSharedMemorySize, SMEM_SZ);
    cudaFuncSetAttribute(gemm_kernel<false>,
                         cudaFuncAttributeMaxDynamicSharedMemorySize, SMEM_SZ);

    // weight prep + node embed
    wprep_kernel<<<HH, HH>>>(W1, pw1ah, pw1al);
    wprep_kernel<<<HH, HH>>>(W1 + (size_t)HH * HH, pw1bh, pw1bl);
    wprep_kernel<<<HH, HH>>>(W2, pw2h, pw2l);
    node_embed_kernel<<<NN / 16, HH>>>(feat, pos, W_in, b_in);

    // z = x[sup] @ W1_bot + b1
    gemm_kernel<true><<<(SS / 128) * 2, 256, SMEM_SZ>>>(
        pxh, pxl, pw1bh, pw1bl, sup, b1, pz);

    // y = x @ W1_top (big GEMM)
    gemm_kernel<false><<<(NN / 128) * 2, 256, SMEM_SZ>>>(
        pxh, pxl, pw1ah, pw1al, nullptr, nullptr, py);

    // pool[s] = mean_e GELU(y[src_e] + z[s])
    pool_kernel<<<SS / 4, HH>>>(src);

    // out = pool @ W2 + b2
    gemm_kernel<false><<<(SS / 128) * 2, 256, SMEM_SZ>>>(
        pph, ppl, pw2h, pw2l, nullptr, b2, out);
}